// round 1
// baseline (speedup 1.0000x reference)
#include <cuda_runtime.h>
#include <cstdint>

#define F 128
#define F4 (F/4)
#define MAX_ATOMS 20000

// Scratch (allocation-free rule: __device__ globals)
__device__ float4 g_V[MAX_ATOMS * 3 * F4];   // V[i][c][f] accumulators, 30.7 MB
__device__ float  g_T[MAX_ATOMS * 3 * F];    // T = V @ W^T, 30.7 MB
__device__ int    g_cnt[MAX_ATOMS];          // pairs-per-atom (for bias term)

__device__ __forceinline__ void red_add_v4(float* addr, float4 v) {
    asm volatile("red.global.add.v4.f32 [%0], {%1,%2,%3,%4};"
                 :: "l"(addr), "f"(v.x), "f"(v.y), "f"(v.z), "f"(v.w)
                 : "memory");
}

// ---------------------------------------------------------------------------
// K1: zero V accumulators, counters, and the radial half of d_out
// ---------------------------------------------------------------------------
__global__ void zero_kernel(float* __restrict__ out, int n_atoms) {
    int idx = blockIdx.x * blockDim.x + threadIdx.x;
    int stride = gridDim.x * blockDim.x;
    int nv = n_atoms * 3 * F4;
    for (int k = idx; k < nv; k += stride)
        g_V[k] = make_float4(0.f, 0.f, 0.f, 0.f);
    int nr = n_atoms * F;
    for (int k = idx; k < nr; k += stride)
        out[(k >> 7) * (2 * F) + F + (k & (F - 1))] = 0.f;
    for (int k = idx; k < n_atoms; k += stride)
        g_cnt[k] = 0;
}

// ---------------------------------------------------------------------------
// K2: pair scatter. One warp per pair, float4 per lane.
//   radial[i,:] += c * A[j,:]
//   V[i,c,:]    += u_c * c * A[j,:]
// ---------------------------------------------------------------------------
__global__ void pair_kernel(const float4* __restrict__ A4,
                            const int*    __restrict__ pl,
                            const float*  __restrict__ cut,
                            const float*  __restrict__ rij,
                            float*        __restrict__ out,
                            int n_pairs) {
    int p    = (blockIdx.x * blockDim.x + threadIdx.x) >> 5;
    int lane = threadIdx.x & 31;
    if (p >= n_pairs) return;

    int   i  = pl[p];
    int   j  = pl[n_pairs + p];
    float c  = cut[p];
    float r0 = rij[3 * p + 0];
    float r1 = rij[3 * p + 1];
    float r2 = rij[3 * p + 2];
    float inv = rsqrtf(r0 * r0 + r1 * r1 + r2 * r2);
    float ux = r0 * inv, uy = r1 * inv, uz = r2 * inv;

    float4 a = __ldg(&A4[j * F4 + lane]);
    float4 w = make_float4(c * a.x, c * a.y, c * a.z, c * a.w);

    // radial contribution straight into d_out[:, F:2F]
    red_add_v4(out + i * (2 * F) + F + lane * 4, w);

    // three vector channels
    float* vb = (float*)&g_V[(i * 3) * F4 + lane];
    red_add_v4(vb,               make_float4(ux * w.x, ux * w.y, ux * w.z, ux * w.w));
    red_add_v4(vb + F,           make_float4(uy * w.x, uy * w.y, uy * w.z, uy * w.w));
    red_add_v4(vb + 2 * F,       make_float4(uz * w.x, uz * w.y, uz * w.z, uz * w.w));

    if (lane == 0) atomicAdd(&g_cnt[i], 1);
}

// ---------------------------------------------------------------------------
// K3: T[r, g] = sum_f V[r, f] * W[g, f],  r in [0, 3*n_atoms)
// W held in smem padded to 129 floats/row (conflict-free), V tile broadcast.
// Block: 256 threads, 32 rows.
// ---------------------------------------------------------------------------
__global__ void gemm_kernel(const float* __restrict__ Wm, int nrows) {
    extern __shared__ float sm[];
    float* Ws = sm;                 // 128 x 129
    float* Vs = sm + F * (F + 1);   // 32 x 128

    const float* Vg = (const float*)g_V;
    int t = threadIdx.x;

    for (int k = t; k < F * F; k += 256) {
        int g = k >> 7, f = k & (F - 1);
        Ws[g * (F + 1) + f] = Wm[k];
    }
    int r0 = blockIdx.x * 32;
    for (int k = t; k < 32 * F; k += 256) {
        int a = k >> 7, f = k & (F - 1);
        int r = r0 + a;
        Vs[a * F + f] = (r < nrows) ? Vg[r * F + f] : 0.f;
    }
    __syncthreads();

    int g = t & (F - 1);
    int a0 = t >> 7;  // 0 or 1
    float acc[16];
#pragma unroll
    for (int k = 0; k < 16; k++) acc[k] = 0.f;

#pragma unroll 4
    for (int f = 0; f < F; f++) {
        float w = Ws[g * (F + 1) + f];
#pragma unroll
        for (int k = 0; k < 16; k++)
            acc[k] += Vs[(a0 + 2 * k) * F + f] * w;
    }

#pragma unroll
    for (int k = 0; k < 16; k++) {
        int r = r0 + a0 + 2 * k;
        if (r < nrows) g_T[r * F + g] = acc[k];
    }
}

// ---------------------------------------------------------------------------
// K4: norms over the 3 spatial channels (+ bias * pair-count), write out[:, :F]
// ---------------------------------------------------------------------------
__global__ void finalize_kernel(const float* __restrict__ b,
                                float* __restrict__ out, int n_atoms) {
    int idx = blockIdx.x * blockDim.x + threadIdx.x;
    if (idx >= n_atoms * F) return;
    int i = idx >> 7, g = idx & (F - 1);
    float bb = b[g] * (float)g_cnt[i];
    float v0 = g_T[(i * 3 + 0) * F + g] + bb;
    float v1 = g_T[(i * 3 + 1) * F + g] + bb;
    float v2 = g_T[(i * 3 + 2) * F + g] + bb;
    out[i * (2 * F) + g] = sqrtf(v0 * v0 + v1 * v1 + v2 * v2 + 1e-12f);
}

// ---------------------------------------------------------------------------
// Launch
// ---------------------------------------------------------------------------
extern "C" void kernel_launch(void* const* d_in, const int* in_sizes, int n_in,
                              void* d_out, int out_size) {
    const float* A   = (const float*)d_in[0];   // [N, F]
    const int*   pl  = (const int*)  d_in[1];   // [2, P]
    const float* cut = (const float*)d_in[2];   // [P, 1]
    const float* rij = (const float*)d_in[3];   // [P, 3]
    const float* Wm  = (const float*)d_in[4];   // [F, F]
    const float* b   = (const float*)d_in[5];   // [F]
    float* out = (float*)d_out;                 // [N, 2F]

    int n_atoms = in_sizes[0] / F;
    int n_pairs = in_sizes[2];

    // K1: zero scratch + radial output region
    zero_kernel<<<1024, 256>>>(out, n_atoms);

    // K2: pair scatter (1 warp/pair, 8 pairs/block)
    {
        int warps_per_block = 8;
        int grid = (n_pairs + warps_per_block - 1) / warps_per_block;
        pair_kernel<<<grid, warps_per_block * 32>>>(
            (const float4*)A, pl, cut, rij, out, n_pairs);
    }

    // K3: T = V @ W^T
    {
        int nrows = n_atoms * 3;
        int smem = (F * (F + 1) + 32 * F) * (int)sizeof(float);  // 82,432 B
        cudaFuncSetAttribute(gemm_kernel,
                             cudaFuncAttributeMaxDynamicSharedMemorySize, smem);
        int grid = (nrows + 31) / 32;
        gemm_kernel<<<grid, 256, smem>>>(Wm, nrows);
    }

    // K4: norms
    {
        int total = n_atoms * F;
        finalize_kernel<<<(total + 255) / 256, 256>>>(b, out, n_atoms);
    }
}

// round 2
// speedup vs baseline: 1.4656x; 1.4656x over previous
#include <cuda_runtime.h>
#include <cstdint>

#define F 128
#define F4 (F/4)
#define MAX_ATOMS 20000
#define MAX_PAIRS 320000
#define SCAN_THREADS 1024
#define SCAN_PER ((MAX_ATOMS + SCAN_THREADS - 1) / SCAN_THREADS)   // 20

// Scratch (allocation-free rule: __device__ globals)
__device__ float4 g_V[MAX_ATOMS * 3 * F4];     // V[i][c][:] accumulators
__device__ float  g_T[MAX_ATOMS * 3 * F];      // T = V @ W^T
__device__ float  g_Wt[F * F];                 // W transposed: Wt[f][g]
__device__ int    g_cnt[MAX_ATOMS];            // pairs per atom
__device__ int    g_off[MAX_ATOMS];            // bin start offsets
__device__ int    g_cur[MAX_ATOMS];            // scatter cursors
__device__ int    g_recJ[MAX_PAIRS];           // binned: neighbor index j
__device__ float4 g_recU[MAX_PAIRS];           // binned: (ux, uy, uz, cutoff)

// ---------------------------------------------------------------------------
// K1: zero counters + transpose W once (Wt[f][g] = W[g][f])
// ---------------------------------------------------------------------------
__global__ void init_kernel(const float* __restrict__ Wm, int n_atoms) {
    int idx = blockIdx.x * blockDim.x + threadIdx.x;
    if (idx < F * F) {
        int f = idx >> 7, g = idx & (F - 1);
        g_Wt[idx] = Wm[g * F + f];
    }
    if (idx < n_atoms) g_cnt[idx] = 0;
}

// ---------------------------------------------------------------------------
// K2: histogram of idx_i
// ---------------------------------------------------------------------------
__global__ void hist_kernel(const int* __restrict__ pl, int n_pairs) {
    int p = blockIdx.x * blockDim.x + threadIdx.x;
    if (p < n_pairs) atomicAdd(&g_cnt[pl[p]], 1);
}

// ---------------------------------------------------------------------------
// K3: exclusive scan over g_cnt -> g_off, g_cur (single block)
// ---------------------------------------------------------------------------
__global__ void scan_kernel(int n_atoms) {
    __shared__ int ssum[SCAN_THREADS];
    int t = threadIdx.x;
    int base = t * SCAN_PER;
    int local[SCAN_PER];
    int s = 0;
#pragma unroll
    for (int k = 0; k < SCAN_PER; k++) {
        int idx = base + k;
        int v = (idx < n_atoms) ? g_cnt[idx] : 0;
        local[k] = s;
        s += v;
    }
    ssum[t] = s;
    __syncthreads();
    for (int d = 1; d < SCAN_THREADS; d <<= 1) {
        int x = (t >= d) ? ssum[t - d] : 0;
        __syncthreads();
        ssum[t] += x;
        __syncthreads();
    }
    int excl = (t > 0) ? ssum[t - 1] : 0;
#pragma unroll
    for (int k = 0; k < SCAN_PER; k++) {
        int idx = base + k;
        if (idx < n_atoms) {
            int o = excl + local[k];
            g_off[idx] = o;
            g_cur[idx] = o;
        }
    }
}

// ---------------------------------------------------------------------------
// K4: scatter pairs into bins (record = j, (ux,uy,uz,c))
// ---------------------------------------------------------------------------
__global__ void scatter_kernel(const int* __restrict__ pl,
                               const float* __restrict__ cut,
                               const float* __restrict__ rij,
                               int n_pairs) {
    int p = blockIdx.x * blockDim.x + threadIdx.x;
    if (p >= n_pairs) return;
    int   i = pl[p];
    int   j = pl[n_pairs + p];
    float c = cut[p];
    float r0 = rij[3 * p + 0];
    float r1 = rij[3 * p + 1];
    float r2 = rij[3 * p + 2];
    float inv = rsqrtf(r0 * r0 + r1 * r1 + r2 * r2);
    int pos = atomicAdd(&g_cur[i], 1);
    g_recJ[pos] = j;
    g_recU[pos] = make_float4(r0 * inv, r1 * inv, r2 * inv, c);
}

// ---------------------------------------------------------------------------
// K5: gather. One warp per atom; accumulate radial + 3 vector channels in
// registers, single store per destination. No atomics.
// ---------------------------------------------------------------------------
__device__ __forceinline__ void acc_pair(const float4& u, const float4& a,
                                         float4& ar, float4& ax, float4& ay, float4& az) {
    float c = u.w;
    float wx = c * a.x, wy = c * a.y, wz = c * a.z, ww = c * a.w;
    ar.x += wx;        ar.y += wy;        ar.z += wz;        ar.w += ww;
    ax.x += u.x * wx;  ax.y += u.x * wy;  ax.z += u.x * wz;  ax.w += u.x * ww;
    ay.x += u.y * wx;  ay.y += u.y * wy;  ay.z += u.y * wz;  ay.w += u.y * ww;
    az.x += u.z * wx;  az.y += u.z * wy;  az.z += u.z * wz;  az.w += u.z * ww;
}

__global__ void gather_kernel(const float4* __restrict__ A4,
                              float* __restrict__ out, int n_atoms) {
    int w    = (blockIdx.x * blockDim.x + threadIdx.x) >> 5;
    int lane = threadIdx.x & 31;
    if (w >= n_atoms) return;
    int n = g_cnt[w];
    int base = g_off[w];

    float4 ar = make_float4(0.f, 0.f, 0.f, 0.f);
    float4 ax = ar, ay = ar, az = ar;

    int k = 0;
    for (; k + 1 < n; k += 2) {
        int j0 = g_recJ[base + k];
        int j1 = g_recJ[base + k + 1];
        float4 u0 = g_recU[base + k];
        float4 u1 = g_recU[base + k + 1];
        float4 a0 = __ldg(&A4[j0 * F4 + lane]);
        float4 a1 = __ldg(&A4[j1 * F4 + lane]);
        acc_pair(u0, a0, ar, ax, ay, az);
        acc_pair(u1, a1, ar, ax, ay, az);
    }
    if (k < n) {
        int j0 = g_recJ[base + k];
        float4 u0 = g_recU[base + k];
        float4 a0 = __ldg(&A4[j0 * F4 + lane]);
        acc_pair(u0, a0, ar, ax, ay, az);
    }

    // radial straight into d_out[:, F:2F]
    *(float4*)(out + w * (2 * F) + F + lane * 4) = ar;
    g_V[(w * 3 + 0) * F4 + lane] = ax;
    g_V[(w * 3 + 1) * F4 + lane] = ay;
    g_V[(w * 3 + 2) * F4 + lane] = az;
}

// ---------------------------------------------------------------------------
// K6: T = V @ W^T with packed fp32 FFMA2 (fma.rn.f32x2).
// 32-row tiles, 256 threads; smem: Wt[f][g] (64KB) + V duplicated (v,v) (32KB).
// Mainloop per f per thread: 1 LDS.128 (W) + 4 LDS.64 (V bcast) + 8 FFMA2.
// ---------------------------------------------------------------------------
#define GR 32
__global__ void gemm_kernel(int nrows) {
    extern __shared__ char smraw[];
    float*  Ws = (float*)smraw;                        // [F][F]
    float2* Vs = (float2*)(smraw + F * F * 4);         // [GR][F] as (v,v)

    int t  = threadIdx.x;
    int r0 = blockIdx.x * GR;

    // stage W^T (precomputed globally)
    float4* Ws4 = (float4*)Ws;
    const float4* Wt4 = (const float4*)g_Wt;
    for (int kk = t; kk < F * F / 4; kk += 256) Ws4[kk] = Wt4[kk];

    // stage V rows, duplicated into f32x2 lanes
    const float4* Vg4 = (const float4*)g_V;
    for (int kk = t; kk < GR * F4; kk += 256) {
        int a = kk >> 5, f4 = kk & 31;
        int r = r0 + a;
        float4 v = (r < nrows) ? Vg4[r * F4 + f4] : make_float4(0.f, 0.f, 0.f, 0.f);
        float2* d = &Vs[a * F + f4 * 4];
        d[0] = make_float2(v.x, v.x);
        d[1] = make_float2(v.y, v.y);
        d[2] = make_float2(v.z, v.z);
        d[3] = make_float2(v.w, v.w);
    }
    __syncthreads();

    int gx = t & 31;      // col group: g = gx*4 .. +3
    int gy = t >> 5;      // row group: rows gy*4 .. +3
    unsigned long long acc[4][2] = {};
    const unsigned long long* VsU = (const unsigned long long*)Vs;

#pragma unroll 4
    for (int f = 0; f < F; f++) {
        float4 w4 = *(const float4*)&Ws[f * F + gx * 4];
        unsigned long long w01, w23;
        asm("mov.b64 %0, {%1, %2};" : "=l"(w01) : "f"(w4.x), "f"(w4.y));
        asm("mov.b64 %0, {%1, %2};" : "=l"(w23) : "f"(w4.z), "f"(w4.w));
#pragma unroll
        for (int r = 0; r < 4; r++) {
            unsigned long long v = VsU[(gy * 4 + r) * F + f];
            asm("fma.rn.f32x2 %0, %1, %2, %0;" : "+l"(acc[r][0]) : "l"(v), "l"(w01));
            asm("fma.rn.f32x2 %0, %1, %2, %0;" : "+l"(acc[r][1]) : "l"(v), "l"(w23));
        }
    }

#pragma unroll
    for (int r = 0; r < 4; r++) {
        int row = r0 + gy * 4 + r;
        if (row < nrows) {
            float x0, x1, x2, x3;
            asm("mov.b64 {%0, %1}, %2;" : "=f"(x0), "=f"(x1) : "l"(acc[r][0]));
            asm("mov.b64 {%0, %1}, %2;" : "=f"(x2), "=f"(x3) : "l"(acc[r][1]));
            *(float4*)&g_T[row * F + gx * 4] = make_float4(x0, x1, x2, x3);
        }
    }
}

// ---------------------------------------------------------------------------
// K7: norms over the 3 spatial channels (+ bias * pair-count)
// ---------------------------------------------------------------------------
__global__ void finalize_kernel(const float* __restrict__ b,
                                float* __restrict__ out, int n_atoms) {
    int idx = blockIdx.x * blockDim.x + threadIdx.x;
    if (idx >= n_atoms * F) return;
    int i = idx >> 7, g = idx & (F - 1);
    float bb = b[g] * (float)g_cnt[i];
    float v0 = g_T[(i * 3 + 0) * F + g] + bb;
    float v1 = g_T[(i * 3 + 1) * F + g] + bb;
    float v2 = g_T[(i * 3 + 2) * F + g] + bb;
    out[i * (2 * F) + g] = sqrtf(v0 * v0 + v1 * v1 + v2 * v2 + 1e-12f);
}

// ---------------------------------------------------------------------------
// Launch
// ---------------------------------------------------------------------------
extern "C" void kernel_launch(void* const* d_in, const int* in_sizes, int n_in,
                              void* d_out, int out_size) {
    const float* A   = (const float*)d_in[0];   // [N, F]
    const int*   pl  = (const int*)  d_in[1];   // [2, P]
    const float* cut = (const float*)d_in[2];   // [P, 1]
    const float* rij = (const float*)d_in[3];   // [P, 3]
    const float* Wm  = (const float*)d_in[4];   // [F, F]
    const float* b   = (const float*)d_in[5];   // [F]
    float* out = (float*)d_out;                 // [N, 2F]

    int n_atoms = in_sizes[0] / F;
    int n_pairs = in_sizes[2];

    int init_n = (n_atoms > F * F) ? n_atoms : F * F;
    init_kernel<<<(init_n + 255) / 256, 256>>>(Wm, n_atoms);

    hist_kernel<<<(n_pairs + 255) / 256, 256>>>(pl, n_pairs);

    scan_kernel<<<1, SCAN_THREADS>>>(n_atoms);

    scatter_kernel<<<(n_pairs + 255) / 256, 256>>>(pl, cut, rij, n_pairs);

    {
        int warps_per_block = 8;
        int grid = (n_atoms + warps_per_block - 1) / warps_per_block;
        gather_kernel<<<grid, warps_per_block * 32>>>((const float4*)A, out, n_atoms);
    }

    {
        int nrows = n_atoms * 3;
        int smem = (F * F) * 4 + GR * F * 8;  // 64KB + 32KB = 96KB
        cudaFuncSetAttribute(gemm_kernel,
                             cudaFuncAttributeMaxDynamicSharedMemorySize, smem);
        int grid = (nrows + GR - 1) / GR;
        gemm_kernel<<<grid, 256, smem>>>(nrows);
    }

    {
        int total = n_atoms * F;
        finalize_kernel<<<(total + 255) / 256, 256>>>(b, out, n_atoms);
    }
}

// round 3
// speedup vs baseline: 1.6766x; 1.1440x over previous
#include <cuda_runtime.h>
#include <cstdint>

#define F 128
#define F4 (F/4)
#define MAX_ATOMS 20000
#define MAX_PAIRS 320000
#define SCAN_THREADS 1024
#define SCAN_PER ((MAX_ATOMS + SCAN_THREADS - 1) / SCAN_THREADS)   // 20

// GEMM tile config
#define GA 8                 // atoms per tile (24 rows)
#define GT 256               // threads per gemm block
#define VS_STRIDE 134        // padded u64 row stride (even, 3*134*8 % 128 == 16 -> conflict-free)

// Scratch (allocation-free rule: __device__ globals)
__device__ float4 g_V[MAX_ATOMS * 3 * F4];     // V[i][c][:] accumulators
__device__ float  g_Wt[F * F];                 // Wt[f][g] = W[g][f]
__device__ int    g_cnt[MAX_ATOMS];            // pairs per atom
__device__ int    g_off[MAX_ATOMS];            // bin start offsets
__device__ int    g_cur[MAX_ATOMS];            // scatter cursors
__device__ int    g_recJ[MAX_PAIRS];           // binned: neighbor index j
__device__ float4 g_recU[MAX_PAIRS];           // binned: (ux, uy, uz, cutoff)

__device__ __forceinline__ unsigned long long pack64(float a, float b) {
    unsigned long long r;
    asm("mov.b64 %0, {%1, %2};" : "=l"(r) : "f"(a), "f"(b));
    return r;
}
__device__ __forceinline__ float2 unpack64(unsigned long long v) {
    float2 r;
    asm("mov.b64 {%0, %1}, %2;" : "=f"(r.x), "=f"(r.y) : "l"(v));
    return r;
}

// ---------------------------------------------------------------------------
// K1: zero counters + transpose W once (Wt[f][g] = W[g][f])
// ---------------------------------------------------------------------------
__global__ void init_kernel(const float* __restrict__ Wm, int n_atoms) {
    int idx = blockIdx.x * blockDim.x + threadIdx.x;
    if (idx < F * F) {
        int f = idx >> 7, g = idx & (F - 1);
        g_Wt[idx] = Wm[g * F + f];
    }
    if (idx < n_atoms) g_cnt[idx] = 0;
}

// ---------------------------------------------------------------------------
// K2: histogram of idx_i
// ---------------------------------------------------------------------------
__global__ void hist_kernel(const int* __restrict__ pl, int n_pairs) {
    int b0 = blockIdx.x * (blockDim.x * 4) + threadIdx.x;
#pragma unroll
    for (int q = 0; q < 4; q++) {
        int p = b0 + q * blockDim.x;
        if (p < n_pairs) atomicAdd(&g_cnt[pl[p]], 1);
    }
}

// ---------------------------------------------------------------------------
// K3: exclusive scan over g_cnt -> g_off, g_cur (single block)
// ---------------------------------------------------------------------------
__global__ void scan_kernel(int n_atoms) {
    __shared__ int ssum[SCAN_THREADS];
    int t = threadIdx.x;
    int base = t * SCAN_PER;
    int local[SCAN_PER];
    int s = 0;
#pragma unroll
    for (int k = 0; k < SCAN_PER; k++) {
        int idx = base + k;
        int v = (idx < n_atoms) ? g_cnt[idx] : 0;
        local[k] = s;
        s += v;
    }
    ssum[t] = s;
    __syncthreads();
    for (int d = 1; d < SCAN_THREADS; d <<= 1) {
        int x = (t >= d) ? ssum[t - d] : 0;
        __syncthreads();
        ssum[t] += x;
        __syncthreads();
    }
    int excl = (t > 0) ? ssum[t - 1] : 0;
#pragma unroll
    for (int k = 0; k < SCAN_PER; k++) {
        int idx = base + k;
        if (idx < n_atoms) {
            int o = excl + local[k];
            g_off[idx] = o;
            g_cur[idx] = o;
        }
    }
}

// ---------------------------------------------------------------------------
// K4: scatter pairs into bins; 4 pairs/thread for MLP on the atomic chain
// ---------------------------------------------------------------------------
__global__ void scatter_kernel(const int* __restrict__ pl,
                               const float* __restrict__ cut,
                               const float* __restrict__ rij,
                               int n_pairs) {
    int b0 = blockIdx.x * (blockDim.x * 4) + threadIdx.x;
#pragma unroll
    for (int q = 0; q < 4; q++) {
        int p = b0 + q * blockDim.x;
        if (p < n_pairs) {
            int   i = pl[p];
            int   j = pl[n_pairs + p];
            float c = cut[p];
            float r0 = rij[3 * p + 0];
            float r1 = rij[3 * p + 1];
            float r2 = rij[3 * p + 2];
            float inv = rsqrtf(r0 * r0 + r1 * r1 + r2 * r2);
            int pos = atomicAdd(&g_cur[i], 1);
            g_recJ[pos] = j;
            g_recU[pos] = make_float4(r0 * inv, r1 * inv, r2 * inv, c);
        }
    }
}

// ---------------------------------------------------------------------------
// K5: gather. One warp per atom. Records loaded lane-parallel in 32-chunks,
// distributed via shfl; A gathers unrolled 4-wide (independent chains).
// ---------------------------------------------------------------------------
__device__ __forceinline__ void acc_pair(float ux, float uy, float uz, float c,
                                         const float4& a,
                                         float4& ar, float4& ax, float4& ay, float4& az) {
    float wx = c * a.x, wy = c * a.y, wz = c * a.z, ww = c * a.w;
    ar.x += wx;       ar.y += wy;       ar.z += wz;       ar.w += ww;
    ax.x += ux * wx;  ax.y += ux * wy;  ax.z += ux * wz;  ax.w += ux * ww;
    ay.x += uy * wx;  ay.y += uy * wy;  ay.z += uy * wz;  ay.w += uy * ww;
    az.x += uz * wx;  az.y += uz * wy;  az.z += uz * wz;  az.w += uz * ww;
}

__global__ void gather_kernel(const float4* __restrict__ A4,
                              float* __restrict__ out, int n_atoms) {
    int w    = (blockIdx.x * blockDim.x + threadIdx.x) >> 5;
    int lane = threadIdx.x & 31;
    if (w >= n_atoms) return;
    int n = g_cnt[w];
    int base = g_off[w];

    float4 ar = make_float4(0.f, 0.f, 0.f, 0.f);
    float4 ax = ar, ay = ar, az = ar;

    for (int c0 = 0; c0 < n; c0 += 32) {
        int m = n - c0; if (m > 32) m = 32;
        int jv = 0;
        float4 uv = make_float4(0.f, 0.f, 0.f, 0.f);
        if (lane < m) {
            jv = g_recJ[base + c0 + lane];
            uv = g_recU[base + c0 + lane];
        }
        int k = 0;
        for (; k + 4 <= m; k += 4) {
            int j0 = __shfl_sync(0xffffffffu, jv, k + 0);
            int j1 = __shfl_sync(0xffffffffu, jv, k + 1);
            int j2 = __shfl_sync(0xffffffffu, jv, k + 2);
            int j3 = __shfl_sync(0xffffffffu, jv, k + 3);
            float4 a0 = __ldg(&A4[j0 * F4 + lane]);
            float4 a1 = __ldg(&A4[j1 * F4 + lane]);
            float4 a2 = __ldg(&A4[j2 * F4 + lane]);
            float4 a3 = __ldg(&A4[j3 * F4 + lane]);
            float x0 = __shfl_sync(0xffffffffu, uv.x, k + 0);
            float y0 = __shfl_sync(0xffffffffu, uv.y, k + 0);
            float z0 = __shfl_sync(0xffffffffu, uv.z, k + 0);
            float c0f = __shfl_sync(0xffffffffu, uv.w, k + 0);
            float x1 = __shfl_sync(0xffffffffu, uv.x, k + 1);
            float y1 = __shfl_sync(0xffffffffu, uv.y, k + 1);
            float z1 = __shfl_sync(0xffffffffu, uv.z, k + 1);
            float c1f = __shfl_sync(0xffffffffu, uv.w, k + 1);
            float x2 = __shfl_sync(0xffffffffu, uv.x, k + 2);
            float y2 = __shfl_sync(0xffffffffu, uv.y, k + 2);
            float z2 = __shfl_sync(0xffffffffu, uv.z, k + 2);
            float c2f = __shfl_sync(0xffffffffu, uv.w, k + 2);
            float x3 = __shfl_sync(0xffffffffu, uv.x, k + 3);
            float y3 = __shfl_sync(0xffffffffu, uv.y, k + 3);
            float z3 = __shfl_sync(0xffffffffu, uv.z, k + 3);
            float c3f = __shfl_sync(0xffffffffu, uv.w, k + 3);
            acc_pair(x0, y0, z0, c0f, a0, ar, ax, ay, az);
            acc_pair(x1, y1, z1, c1f, a1, ar, ax, ay, az);
            acc_pair(x2, y2, z2, c2f, a2, ar, ax, ay, az);
            acc_pair(x3, y3, z3, c3f, a3, ar, ax, ay, az);
        }
        for (; k < m; k++) {
            int j0 = __shfl_sync(0xffffffffu, jv, k);
            float4 a0 = __ldg(&A4[j0 * F4 + lane]);
            float x0 = __shfl_sync(0xffffffffu, uv.x, k);
            float y0 = __shfl_sync(0xffffffffu, uv.y, k);
            float z0 = __shfl_sync(0xffffffffu, uv.z, k);
            float c0f = __shfl_sync(0xffffffffu, uv.w, k);
            acc_pair(x0, y0, z0, c0f, a0, ar, ax, ay, az);
        }
    }

    // radial half of output
    *(float4*)(out + w * (2 * F) + F + lane * 4) = ar;
    g_V[(w * 3 + 0) * F4 + lane] = ax;
    g_V[(w * 3 + 1) * F4 + lane] = ay;
    g_V[(w * 3 + 2) * F4 + lane] = az;
}

// ---------------------------------------------------------------------------
// K6: fused GEMM + norm. Persistent blocks, W staged once per block.
// Thread = (atom in tile = lane>>2, colgroup = warp*4 + (lane&3)); 3 channel
// rows per thread in FFMA2 (f32x2) accumulators; norm + bias epilogue in-reg.
// ---------------------------------------------------------------------------
__global__ void gemm_norm_kernel(const float* __restrict__ bias,
                                 float* __restrict__ out, int n_atoms) {
    extern __shared__ char smraw[];
    float* Ws = (float*)smraw;                                       // [F][F]
    unsigned long long* VsU = (unsigned long long*)(smraw + F * F * 4); // [24][VS_STRIDE]

    int t = threadIdx.x;
    int warp = t >> 5, lane = t & 31;
    int ga = lane >> 2;                 // atom in tile (0..7)
    int cg = warp * 4 + (lane & 3);     // col group (0..31) -> cols cg*4..+3

    // stage Wt once per block
    {
        const float4* s = (const float4*)g_Wt;
        float4* d = (float4*)Ws;
        for (int k = t; k < F * F / 4; k += GT) d[k] = s[k];
    }
    __syncthreads();

    int tiles = (n_atoms + GA - 1) / GA;
    for (int tile = blockIdx.x; tile < tiles; tile += gridDim.x) {
        int row0 = tile * GA * 3;

        // load V rows to regs (issues before sync -> overlaps prev compute)
        float4 vst[3];
#pragma unroll
        for (int r = 0; r < 3; r++) {
            int idx = t + r * GT;            // 0..767
            int row = idx >> 5, f4 = idx & 31;
            int grow = row0 + row;
            vst[r] = (grow < n_atoms * 3)
                       ? __ldg(&((const float4*)g_V)[grow * F4 + f4])
                       : make_float4(0.f, 0.f, 0.f, 0.f);
        }
        __syncthreads();   // previous tile's compute done
#pragma unroll
        for (int r = 0; r < 3; r++) {
            int idx = t + r * GT;
            int row = idx >> 5, f4 = idx & 31;
            unsigned long long* d = &VsU[row * VS_STRIDE + f4 * 4];
            d[0] = pack64(vst[r].x, vst[r].x);
            d[1] = pack64(vst[r].y, vst[r].y);
            d[2] = pack64(vst[r].z, vst[r].z);
            d[3] = pack64(vst[r].w, vst[r].w);
        }
        __syncthreads();

        unsigned long long acc[3][2] = {};
#pragma unroll 4
        for (int f = 0; f < F; f += 2) {
            float4 w0 = *(const float4*)&Ws[f * F + cg * 4];
            float4 w1 = *(const float4*)&Ws[(f + 1) * F + cg * 4];
            unsigned long long w0a = pack64(w0.x, w0.y), w0b = pack64(w0.z, w0.w);
            unsigned long long w1a = pack64(w1.x, w1.y), w1b = pack64(w1.z, w1.w);
#pragma unroll
            for (int c = 0; c < 3; c++) {
                ulonglong2 vv = *(const ulonglong2*)&VsU[(ga * 3 + c) * VS_STRIDE + f];
                asm("fma.rn.f32x2 %0, %1, %2, %0;" : "+l"(acc[c][0]) : "l"(vv.x), "l"(w0a));
                asm("fma.rn.f32x2 %0, %1, %2, %0;" : "+l"(acc[c][1]) : "l"(vv.x), "l"(w0b));
                asm("fma.rn.f32x2 %0, %1, %2, %0;" : "+l"(acc[c][0]) : "l"(vv.y), "l"(w1a));
                asm("fma.rn.f32x2 %0, %1, %2, %0;" : "+l"(acc[c][1]) : "l"(vv.y), "l"(w1b));
            }
        }

        int atom = tile * GA + ga;
        if (atom < n_atoms) {
            float cnt = (float)g_cnt[atom];
            float4 bv = __ldg((const float4*)&bias[cg * 4]);
            float2 v00 = unpack64(acc[0][0]), v01 = unpack64(acc[0][1]);
            float2 v10 = unpack64(acc[1][0]), v11 = unpack64(acc[1][1]);
            float2 v20 = unpack64(acc[2][0]), v21 = unpack64(acc[2][1]);
            float b0 = bv.x * cnt, b1 = bv.y * cnt, b2 = bv.z * cnt, b3 = bv.w * cnt;
            float4 o;
            {
                float x = v00.x + b0, y = v10.x + b0, z = v20.x + b0;
                o.x = sqrtf(x * x + y * y + z * z + 1e-12f);
            }
            {
                float x = v00.y + b1, y = v10.y + b1, z = v20.y + b1;
                o.y = sqrtf(x * x + y * y + z * z + 1e-12f);
            }
            {
                float x = v01.x + b2, y = v11.x + b2, z = v21.x + b2;
                o.z = sqrtf(x * x + y * y + z * z + 1e-12f);
            }
            {
                float x = v01.y + b3, y = v11.y + b3, z = v21.y + b3;
                o.w = sqrtf(x * x + y * y + z * z + 1e-12f);
            }
            *(float4*)&out[atom * (2 * F) + cg * 4] = o;
        }
    }
}

// ---------------------------------------------------------------------------
// Launch
// ---------------------------------------------------------------------------
extern "C" void kernel_launch(void* const* d_in, const int* in_sizes, int n_in,
                              void* d_out, int out_size) {
    const float* A   = (const float*)d_in[0];   // [N, F]
    const int*   pl  = (const int*)  d_in[1];   // [2, P]
    const float* cut = (const float*)d_in[2];   // [P, 1]
    const float* rij = (const float*)d_in[3];   // [P, 3]
    const float* Wm  = (const float*)d_in[4];   // [F, F]
    const float* b   = (const float*)d_in[5];   // [F]
    float* out = (float*)d_out;                 // [N, 2F]

    int n_atoms = in_sizes[0] / F;
    int n_pairs = in_sizes[2];

    int init_n = (n_atoms > F * F) ? n_atoms : F * F;
    init_kernel<<<(init_n + 255) / 256, 256>>>(Wm, n_atoms);

    hist_kernel<<<(n_pairs + 1023) / 1024, 256>>>(pl, n_pairs);

    scan_kernel<<<1, SCAN_THREADS>>>(n_atoms);

    scatter_kernel<<<(n_pairs + 1023) / 1024, 256>>>(pl, cut, rij, n_pairs);

    {
        int warps_per_block = 8;
        int grid = (n_atoms + warps_per_block - 1) / warps_per_block;
        gather_kernel<<<grid, warps_per_block * 32>>>((const float4*)A, out, n_atoms);
    }

    {
        int smem = F * F * 4 + 3 * GA * VS_STRIDE * 8;   // 64KB + ~25.1KB
        cudaFuncSetAttribute(gemm_norm_kernel,
                             cudaFuncAttributeMaxDynamicSharedMemorySize, smem);
        gemm_norm_kernel<<<296, GT, smem>>>(b, out, n_atoms);
    }
}

// round 4
// speedup vs baseline: 2.0584x; 1.2277x over previous
#include <cuda_runtime.h>
#include <cstdint>

#define F 128
#define F4 (F/4)
#define MAX_ATOMS 20000
#define MAX_PAIRS 320000
#define SCAN_THREADS 1024
#define SCAN_PER ((MAX_ATOMS + SCAN_THREADS - 1) / SCAN_THREADS)   // 20

// GEMM tile config: 16 atoms (48 rows) per tile, 256 threads
#define GA 16
#define GT 256
#define VS_STRIDE 130        // u64 row stride; atom-step mod 8 (16B units) = 3 -> spread

typedef unsigned long long u64;

// Scratch (allocation-free rule: __device__ globals)
__device__ float4 g_V[MAX_ATOMS * 3 * F4];     // V[i][c][:] accumulators
__device__ float  g_Wt[F * F];                 // Wt[f][g] = W[g][f]
__device__ int    g_cnt[MAX_ATOMS];            // pairs per atom
__device__ int    g_off[MAX_ATOMS];            // bin start offsets
__device__ int    g_pos[MAX_PAIRS];            // position of pair within its bin
__device__ int    g_recJ[MAX_PAIRS];           // binned: neighbor index j
__device__ float4 g_recU[MAX_PAIRS];           // binned: (ux, uy, uz, cutoff)

__device__ __forceinline__ u64 pack64(float a, float b) {
    u64 r; asm("mov.b64 %0, {%1, %2};" : "=l"(r) : "f"(a), "f"(b)); return r;
}
__device__ __forceinline__ float2 unpack64(u64 v) {
    float2 r; asm("mov.b64 {%0, %1}, %2;" : "=f"(r.x), "=f"(r.y) : "l"(v)); return r;
}
__device__ __forceinline__ u64 mul2(u64 a, u64 b) {
    u64 r; asm("mul.rn.f32x2 %0, %1, %2;" : "=l"(r) : "l"(a), "l"(b)); return r;
}
__device__ __forceinline__ u64 add2(u64 a, u64 b) {
    u64 r; asm("add.rn.f32x2 %0, %1, %2;" : "=l"(r) : "l"(a), "l"(b)); return r;
}
#define FMA2(acc, a, b) asm("fma.rn.f32x2 %0, %1, %2, %0;" : "+l"(acc) : "l"(a), "l"(b))

// ---------------------------------------------------------------------------
// K1: zero counters + transpose W once (Wt[f][g] = W[g][f])
// ---------------------------------------------------------------------------
__global__ void init_kernel(const float* __restrict__ Wm, int n_atoms) {
    int idx = blockIdx.x * blockDim.x + threadIdx.x;
    if (idx < F * F) {
        int f = idx >> 7, g = idx & (F - 1);
        g_Wt[idx] = Wm[g * F + f];
    }
    if (idx < n_atoms) g_cnt[idx] = 0;
}

// ---------------------------------------------------------------------------
// K2: histogram of idx_i + record within-bin position
// ---------------------------------------------------------------------------
__global__ void hist_kernel(const int* __restrict__ pl, int n_pairs) {
    int p = blockIdx.x * blockDim.x + threadIdx.x;
    if (p < n_pairs) g_pos[p] = atomicAdd(&g_cnt[pl[p]], 1);
}

// ---------------------------------------------------------------------------
// K3: exclusive scan over g_cnt -> g_off (single block)
// ---------------------------------------------------------------------------
__global__ void scan_kernel(int n_atoms) {
    __shared__ int ssum[SCAN_THREADS];
    int t = threadIdx.x;
    int base = t * SCAN_PER;
    int local[SCAN_PER];
    int s = 0;
#pragma unroll
    for (int k = 0; k < SCAN_PER; k++) {
        int idx = base + k;
        int v = (idx < n_atoms) ? g_cnt[idx] : 0;
        local[k] = s;
        s += v;
    }
    ssum[t] = s;
    __syncthreads();
    for (int d = 1; d < SCAN_THREADS; d <<= 1) {
        int x = (t >= d) ? ssum[t - d] : 0;
        __syncthreads();
        ssum[t] += x;
        __syncthreads();
    }
    int excl = (t > 0) ? ssum[t - 1] : 0;
#pragma unroll
    for (int k = 0; k < SCAN_PER; k++) {
        int idx = base + k;
        if (idx < n_atoms) g_off[idx] = excl + local[k];
    }
}

// ---------------------------------------------------------------------------
// K4: scatter pairs into bins — NO atomics (position precomputed in hist)
// ---------------------------------------------------------------------------
__global__ void scatter_kernel(const int* __restrict__ pl,
                               const float* __restrict__ cut,
                               const float* __restrict__ rij,
                               int n_pairs) {
    int p = blockIdx.x * blockDim.x + threadIdx.x;
    if (p >= n_pairs) return;
    int   i = pl[p];
    int   j = pl[n_pairs + p];
    float c = cut[p];
    float r0 = rij[3 * p + 0];
    float r1 = rij[3 * p + 1];
    float r2 = rij[3 * p + 2];
    float inv = rsqrtf(r0 * r0 + r1 * r1 + r2 * r2);
    int pos = g_off[i] + g_pos[p];
    g_recJ[pos] = j;
    g_recU[pos] = make_float4(r0 * inv, r1 * inv, r2 * inv, c);
}

// ---------------------------------------------------------------------------
// K5: gather. One warp per atom. Records staged in smem (LDS broadcast, no
// SHFL); accumulation in packed f32x2 (halves FMA issue).
// ---------------------------------------------------------------------------
struct Acc2 { u64 r0, r1, x0, x1, y0, y1, z0, z1; };

__device__ __forceinline__ void acc2(const float4& u, const ulonglong2& a, Acc2& s) {
    u64 cc = pack64(u.w, u.w);
    u64 xx = pack64(u.x, u.x);
    u64 yy = pack64(u.y, u.y);
    u64 zz = pack64(u.z, u.z);
    u64 w0 = mul2(cc, a.x);
    u64 w1 = mul2(cc, a.y);
    s.r0 = add2(s.r0, w0);  s.r1 = add2(s.r1, w1);
    FMA2(s.x0, xx, w0);     FMA2(s.x1, xx, w1);
    FMA2(s.y0, yy, w0);     FMA2(s.y1, yy, w1);
    FMA2(s.z0, zz, w0);     FMA2(s.z1, zz, w1);
}

__global__ void gather_kernel(const ulonglong2* __restrict__ A2,
                              float* __restrict__ out, int n_atoms) {
    __shared__ int    sJ[8][32];
    __shared__ float4 sU[8][32];

    int warp = threadIdx.x >> 5, lane = threadIdx.x & 31;
    int w = blockIdx.x * 8 + warp;
    if (w >= n_atoms) return;
    int n = g_cnt[w];
    int base = g_off[w];

    Acc2 s = {};

    for (int c0 = 0; c0 < n; c0 += 32) {
        int m = n - c0; if (m > 32) m = 32;
        if (lane < m) {
            sJ[warp][lane] = g_recJ[base + c0 + lane];
            sU[warp][lane] = g_recU[base + c0 + lane];
        }
        __syncwarp();
        int k = 0;
        for (; k + 4 <= m; k += 4) {
            int j0 = sJ[warp][k + 0];
            int j1 = sJ[warp][k + 1];
            int j2 = sJ[warp][k + 2];
            int j3 = sJ[warp][k + 3];
            ulonglong2 a0 = __ldg(&A2[j0 * F4 + lane]);
            ulonglong2 a1 = __ldg(&A2[j1 * F4 + lane]);
            ulonglong2 a2 = __ldg(&A2[j2 * F4 + lane]);
            ulonglong2 a3 = __ldg(&A2[j3 * F4 + lane]);
            float4 u0 = sU[warp][k + 0];
            float4 u1 = sU[warp][k + 1];
            float4 u2 = sU[warp][k + 2];
            float4 u3 = sU[warp][k + 3];
            acc2(u0, a0, s); acc2(u1, a1, s); acc2(u2, a2, s); acc2(u3, a3, s);
        }
        for (; k < m; k++) {
            int j0 = sJ[warp][k];
            ulonglong2 a0 = __ldg(&A2[j0 * F4 + lane]);
            float4 u0 = sU[warp][k];
            acc2(u0, a0, s);
        }
        __syncwarp();
    }

    float2 p0, p1;
    // radial half of output
    p0 = unpack64(s.r0); p1 = unpack64(s.r1);
    *(float4*)(out + w * (2 * F) + F + lane * 4) = make_float4(p0.x, p0.y, p1.x, p1.y);
    p0 = unpack64(s.x0); p1 = unpack64(s.x1);
    g_V[(w * 3 + 0) * F4 + lane] = make_float4(p0.x, p0.y, p1.x, p1.y);
    p0 = unpack64(s.y0); p1 = unpack64(s.y1);
    g_V[(w * 3 + 1) * F4 + lane] = make_float4(p0.x, p0.y, p1.x, p1.y);
    p0 = unpack64(s.z0); p1 = unpack64(s.z1);
    g_V[(w * 3 + 2) * F4 + lane] = make_float4(p0.x, p0.y, p1.x, p1.y);
}

// ---------------------------------------------------------------------------
// K6: fused GEMM + norm. Persistent blocks; W staged once (natural float
// layout -> ulonglong2 view gives (w_g, w_g+1) lanes, zero packing).
// Thread = (atom = t&15, colgroup = t>>4 covering 8 cols); 3 channel rows in
// f32x2 accumulators; norm + bias epilogue in-register.
// ---------------------------------------------------------------------------
__global__ void gemm_norm_kernel(const float* __restrict__ bias,
                                 float* __restrict__ out, int n_atoms) {
    extern __shared__ char smraw[];
    float* Ws = (float*)smraw;                        // [F][F] floats
    u64*   VsU = (u64*)(smraw + F * F * 4);           // [48][VS_STRIDE] dup (v,v)

    int t = threadIdx.x;
    int ga = t & 15;            // atom in tile
    int cg = t >> 4;            // col group (0..15) -> cols cg*8..+7
    const ulonglong2* WsU2 = (const ulonglong2*)Ws;   // row stride 32 ull2

    // stage Wt once per block
    {
        const float4* src = (const float4*)g_Wt;
        float4* dst = (float4*)Ws;
        for (int k = t; k < F * F / 4; k += GT) dst[k] = src[k];
    }
    __syncthreads();

    int nrows3 = n_atoms * 3;
    int tiles = (n_atoms + GA - 1) / GA;
    for (int tile = blockIdx.x; tile < tiles; tile += gridDim.x) {
        int row0 = tile * GA * 3;

        // load V rows to regs first (overlaps with previous tile's compute)
        float4 vst[6];
#pragma unroll
        for (int r = 0; r < 6; r++) {
            int idx = t + r * GT;            // 0..1535
            int row = idx >> 5, f4 = idx & 31;
            int grow = row0 + row;
            vst[r] = (grow < nrows3)
                       ? __ldg(&((const float4*)g_V)[grow * F4 + f4])
                       : make_float4(0.f, 0.f, 0.f, 0.f);
        }
        __syncthreads();
#pragma unroll
        for (int r = 0; r < 6; r++) {
            int idx = t + r * GT;
            int row = idx >> 5, f4 = idx & 31;
            ulonglong2 q0, q1;
            q0.x = pack64(vst[r].x, vst[r].x);
            q0.y = pack64(vst[r].y, vst[r].y);
            q1.x = pack64(vst[r].z, vst[r].z);
            q1.y = pack64(vst[r].w, vst[r].w);
            *(ulonglong2*)&VsU[row * VS_STRIDE + f4 * 4]     = q0;
            *(ulonglong2*)&VsU[row * VS_STRIDE + f4 * 4 + 2] = q1;
        }
        __syncthreads();

        u64 acc[3][4] = {};
#pragma unroll 4
        for (int f = 0; f < F; f += 2) {
            ulonglong2 wa0 = WsU2[f * 32 + cg * 2];
            ulonglong2 wa1 = WsU2[f * 32 + cg * 2 + 1];
            ulonglong2 wb0 = WsU2[(f + 1) * 32 + cg * 2];
            ulonglong2 wb1 = WsU2[(f + 1) * 32 + cg * 2 + 1];
#pragma unroll
            for (int c = 0; c < 3; c++) {
                ulonglong2 v = *(const ulonglong2*)&VsU[(ga * 3 + c) * VS_STRIDE + f];
                FMA2(acc[c][0], v.x, wa0.x);
                FMA2(acc[c][1], v.x, wa0.y);
                FMA2(acc[c][2], v.x, wa1.x);
                FMA2(acc[c][3], v.x, wa1.y);
                FMA2(acc[c][0], v.y, wb0.x);
                FMA2(acc[c][1], v.y, wb0.y);
                FMA2(acc[c][2], v.y, wb1.x);
                FMA2(acc[c][3], v.y, wb1.y);
            }
        }

        int atom = tile * GA + ga;
        if (atom < n_atoms) {
            float cnt = (float)g_cnt[atom];
            float4 bv0 = __ldg((const float4*)&bias[cg * 8]);
            float4 bv1 = __ldg((const float4*)&bias[cg * 8 + 4]);
            float ob[8], bb[8];
            bb[0] = bv0.x * cnt; bb[1] = bv0.y * cnt; bb[2] = bv0.z * cnt; bb[3] = bv0.w * cnt;
            bb[4] = bv1.x * cnt; bb[5] = bv1.y * cnt; bb[6] = bv1.z * cnt; bb[7] = bv1.w * cnt;
#pragma unroll
            for (int q = 0; q < 4; q++) {
                float2 vx = unpack64(acc[0][q]);
                float2 vy = unpack64(acc[1][q]);
                float2 vz = unpack64(acc[2][q]);
                float x0 = vx.x + bb[2 * q], y0 = vy.x + bb[2 * q], z0 = vz.x + bb[2 * q];
                float x1 = vx.y + bb[2 * q + 1], y1 = vy.y + bb[2 * q + 1], z1 = vz.y + bb[2 * q + 1];
                ob[2 * q]     = sqrtf(x0 * x0 + y0 * y0 + z0 * z0 + 1e-12f);
                ob[2 * q + 1] = sqrtf(x1 * x1 + y1 * y1 + z1 * z1 + 1e-12f);
            }
            float* o = &out[atom * (2 * F) + cg * 8];
            *(float4*)o       = make_float4(ob[0], ob[1], ob[2], ob[3]);
            *(float4*)(o + 4) = make_float4(ob[4], ob[5], ob[6], ob[7]);
        }
    }
}

// ---------------------------------------------------------------------------
// Launch
// ---------------------------------------------------------------------------
extern "C" void kernel_launch(void* const* d_in, const int* in_sizes, int n_in,
                              void* d_out, int out_size) {
    const float* A   = (const float*)d_in[0];   // [N, F]
    const int*   pl  = (const int*)  d_in[1];   // [2, P]
    const float* cut = (const float*)d_in[2];   // [P, 1]
    const float* rij = (const float*)d_in[3];   // [P, 3]
    const float* Wm  = (const float*)d_in[4];   // [F, F]
    const float* b   = (const float*)d_in[5];   // [F]
    float* out = (float*)d_out;                 // [N, 2F]

    int n_atoms = in_sizes[0] / F;
    int n_pairs = in_sizes[2];

    int init_n = (n_atoms > F * F) ? n_atoms : F * F;
    init_kernel<<<(init_n + 255) / 256, 256>>>(Wm, n_atoms);

    hist_kernel<<<(n_pairs + 255) / 256, 256>>>(pl, n_pairs);

    scan_kernel<<<1, SCAN_THREADS>>>(n_atoms);

    scatter_kernel<<<(n_pairs + 255) / 256, 256>>>(pl, cut, rij, n_pairs);

    gather_kernel<<<(n_atoms + 7) / 8, 256>>>((const ulonglong2*)A, out, n_atoms);

    {
        int smem = F * F * 4 + 3 * GA * VS_STRIDE * 8;   // 64KB + 49.9KB
        cudaFuncSetAttribute(gemm_norm_kernel,
                             cudaFuncAttributeMaxDynamicSharedMemorySize, smem);
        gemm_norm_kernel<<<296, GT, smem>>>(b, out, n_atoms);
    }
}